// round 9
// baseline (speedup 1.0000x reference)
#include <cuda_runtime.h>
#include <math.h>

#define BS 4
#define LEN 2048
#define CIN 32
#define COUT 32
#define HIDDIM 64
#define KTAP 8
#define PADL 7
#define NPOS (BS * LEN)
#define RDIM (CIN * HIDDIM)      // 2048
#define EPSV 1e-5f
#define NWB 16                    // positions per tile (warp per position)
#define THREADS 512
#define NTILE (NPOS / NWB)        // 512
#define NBP 148                   // persistent blocks (<= SM count, all resident)
#define MSPITCH 34                // u64 pitch per channel
#define MAXT 4                    // ceil(NTILE / NBP)

typedef unsigned long long u64;

__device__ double g_stats[2 * COUT];
__device__ int    g_done;
__device__ int    g_fin;

// ---- register-pure packed helpers ----
#define FMA2(d, a, b, c) \
    asm("fma.rn.f32x2 %0, %1, %2, %3;" : "=l"(d) : "l"(a), "l"(b), "l"(c))

__device__ __forceinline__ u64 pack2(float x, float y) {
    u64 d; asm("mov.b64 %0, {%1, %2};" : "=l"(d) : "f"(x), "f"(y)); return d;
}
__device__ __forceinline__ u64 packdup(float x) {
    u64 d; asm("mov.b64 %0, {%1, %1};" : "=l"(d) : "f"(x)); return d;
}
__device__ __forceinline__ void unpack2(u64 v, float& x, float& y) {
    asm("mov.b64 {%0, %1}, %2;" : "=f"(x), "=f"(y) : "l"(v));
}

// mask dtype hedge (byte 1 nonzero <=> 1-byte storage; else 4-byte words)
__device__ __forceinline__ bool mask_at(const void* m, int idx, bool byte_mode) {
    if (byte_mode) return ((const unsigned char*)m)[idx] != 0;
    return ((const unsigned int*)m)[idx] != 0u;
}

struct SmemT {
    float W1s[CIN * HIDDIM];      // 8KB
    float b1s[HIDDIM];
    float b2s[CIN * COUT];        // 4KB
    float wsk[CIN * COUT];        // 4KB
    float bsk[COUT];
    float ff[NWB][CIN];           // 2KB
    float fs[NWB][CIN];           // 2KB
    float ssum[COUT], ssq[COUT];
    float sc[COUT], sb[COUT];
    int   pflag[NWB];
    union alignas(16) {
        struct {
            float teu[NWB][CIN][KTAP];    // 16KB
            float hb[NWB][KTAP][HIDDIM];  // 32KB
        } a;
        float red[NWB][NWB][COUT];        // 32KB
    } u;
    u64 Msu[NWB][CIN * MSPITCH];  // 136KB
};

// load one chunk's W2 pair-registers: chunk cc of warp wid, output lane o
__device__ __forceinline__ void load_wq(const float* __restrict__ W2,
                                        int wid, int lane, int cc, u64* wq) {
    int c  = 2 * wid + (cc >> 1);
    int j0 = (cc & 1) * 32;
    const float* w2base = W2 + (size_t)j0 * (CIN * COUT) + c * COUT + lane;
#pragma unroll
    for (int q = 0; q < 16; q++) {
        float w0 = w2base[(2 * q) * (CIN * COUT)];
        float w1 = w2base[(2 * q + 1) * (CIN * COUT)];
        wq[q] = pack2(w0, w1);
    }
}

__global__ __launch_bounds__(THREADS, 1)
void kpers(const float* __restrict__ times,
           const float* __restrict__ features,
           const void*  __restrict__ mask,
           const float* __restrict__ W1,
           const float* __restrict__ b1,
           const float* __restrict__ W2,
           const float* __restrict__ b2,
           const float* __restrict__ Wskip,
           const float* __restrict__ bskip,
           const float* __restrict__ gamma,
           const float* __restrict__ beta,
           float* __restrict__ out) {
    extern __shared__ char smem_raw[];
    SmemT* s = (SmemT*)smem_raw;

    int tid  = threadIdx.x;
    int wid  = tid >> 5;
    int lane = tid & 31;

    // ---- stage constants ONCE per persistent block ----
    for (int i = tid; i < CIN * HIDDIM; i += THREADS) s->W1s[i] = W1[i];
    for (int i = tid; i < CIN * COUT; i += THREADS) {
        s->b2s[i] = b2[i];
        s->wsk[i] = Wskip[i];
    }
    if (tid < HIDDIM) s->b1s[tid] = b1[tid];
    if (tid < COUT) {
        s->bsk[tid]  = bskip[tid];
        s->ssum[tid] = 0.0f;
        s->ssq[tid]  = 0.0f;
    }
    __syncthreads();

    bool byte_mode = ((const unsigned char*)mask)[1] != 0;

    float oreg[MAXT];
    float osum = 0.0f, osq = 0.0f;

#pragma unroll
    for (int ti = 0; ti < MAXT; ti++) {
        int tile = blockIdx.x + ti * NBP;
        if (tile >= NTILE) break;

        // ============ phase A: build M row (warp per position) =============
        int p = tile * NWB + wid;
        int b = p >> 11;
        int t = p & (LEN - 1);

        bool mask_t = mask_at(mask, p, byte_mode);
        float t_here = times[p];

        s->ff[wid][lane] = features[(size_t)p * CIN + lane];

        unsigned vmask = 0;
#pragma unroll
        for (int k = 0; k < KTAP; k++) {
            int idx = t - PADL + k;
            bool dm = mask_t && (idx >= 0);
            if (dm) dm = mask_at(mask, b * LEN + idx, byte_mode);
            if (dm) vmask |= (1u << k);
        }
        bool any = (vmask != 0);
        float fsum = 0.0f;

        if (any) {
            float inv_pos = __expf(-(float)(lane >> 1) * (9.210340371976184f / 16.0f));
            float phase   = (lane & 1) ? 1.5707963267948966f : 0.0f;
            float fk[KTAP];
#pragma unroll
            for (int k = 0; k < KTAP; k++) {
                int idx = t - PADL + k;
                float te = 0.0f;
                fk[k] = 0.0f;
                if ((vmask >> k) & 1) {
                    float dt = t_here - times[b * LEN + idx];
                    te = __sinf(dt * inv_pos + phase);
                    fk[k] = features[(size_t)(b * LEN + idx) * CIN + lane];
                }
                s->u.a.teu[wid][lane][k] = te;
                fsum += fk[k];
            }
            __syncwarp();

            // h for all taps, i-outer (lane = j; also j+32)
            u64 hh[4][2];
#pragma unroll
            for (int k2 = 0; k2 < 4; k2++) {
                hh[k2][0] = packdup(s->b1s[lane]);
                hh[k2][1] = packdup(s->b1s[lane + 32]);
            }
#pragma unroll
            for (int i = 0; i < CIN; i++) {
                u64 w0 = packdup(s->W1s[i * HIDDIM + lane]);
                u64 w1 = packdup(s->W1s[i * HIDDIM + lane + 32]);
#pragma unroll
                for (int k2 = 0; k2 < 4; k2++) {
                    u64 tp = *(const u64*)&s->u.a.teu[wid][i][2 * k2];  // bcast
                    FMA2(hh[k2][0], tp, w0, hh[k2][0]);
                    FMA2(hh[k2][1], tp, w1, hh[k2][1]);
                }
            }
#pragma unroll
            for (int k2 = 0; k2 < 4; k2++) {
                float a0, c0, a1, c1;
                unpack2(hh[k2][0], a0, c0);
                unpack2(hh[k2][1], a1, c1);
                s->u.a.hb[wid][2 * k2][lane]          = fmaxf(a0, 0.0f);
                s->u.a.hb[wid][2 * k2 + 1][lane]      = fmaxf(c0, 0.0f);
                s->u.a.hb[wid][2 * k2][lane + 32]     = fmaxf(a1, 0.0f);
                s->u.a.hb[wid][2 * k2 + 1][lane + 32] = fmaxf(c1, 0.0f);
            }
            __syncwarp();

            // M update (lane = channel)
            u64 Macc[32];
#pragma unroll
            for (int q = 0; q < 32; q++) Macc[q] = 0ull;
#pragma unroll
            for (int k = 0; k < KTAP; k++) {
                if (!((vmask >> k) & 1)) continue;     // warp-uniform
                u64 f2 = packdup(fk[k]);
                const ulonglong2* hp2 = (const ulonglong2*)&s->u.a.hb[wid][k][0];
#pragma unroll
                for (int q2 = 0; q2 < 16; q2++) {
                    ulonglong2 hp = hp2[q2];           // broadcast LDS.128
                    FMA2(Macc[2 * q2],     f2, hp.x, Macc[2 * q2]);
                    FMA2(Macc[2 * q2 + 1], f2, hp.y, Macc[2 * q2 + 1]);
                }
            }
#pragma unroll
            for (int q = 0; q < 32; q++) s->Msu[wid][lane * MSPITCH + q] = Macc[q];
        }
        s->fs[wid][lane] = fsum;
        if (lane == 0) s->pflag[wid] = any ? 1 : 0;

        // prefetch chunk 0's W2 strip — latency hidden by the barrier wait
        u64 wq[16];
        load_wq(W2, wid, lane, 0, wq);
        __syncthreads();                               // (1)

        // ============ phase B: [16 x 2048] @ [2048 x 32] ===================
        u64 acc2[NWB];
#pragma unroll
        for (int q = 0; q < NWB; q++) acc2[q] = 0ull;

        for (int cc = 0; cc < 4; cc++) {
            int c   = 2 * wid + (cc >> 1);
            int jb2 = (cc & 1) * 16;
#pragma unroll
            for (int pp = 0; pp < NWB; pp++) {
                if (!s->pflag[pp]) continue;           // warp-uniform skip
                const ulonglong2* mp = (const ulonglong2*)&s->Msu[pp][c * MSPITCH + jb2];
#pragma unroll
                for (int q2 = 0; q2 < 8; q2++) {
                    ulonglong2 m = mp[q2];             // broadcast LDS.128
                    FMA2(acc2[pp], m.x, wq[2 * q2],     acc2[pp]);
                    FMA2(acc2[pp], m.y, wq[2 * q2 + 1], acc2[pp]);
                }
            }
            if (cc < 3) load_wq(W2, wid, lane, cc + 1, wq);
        }
#pragma unroll
        for (int pp = 0; pp < NWB; pp++) {
            float lo, hi;
            unpack2(acc2[pp], lo, hi);
            s->u.red[wid][pp][lane] = lo + hi;
        }
        __syncthreads();                               // (2)

        // ============ epilogue: warp wid finalizes its position ============
        float o = 0.0f;
#pragma unroll
        for (int w = 0; w < NWB; w++) o += s->u.red[w][wid][lane];

        const float4* fs4 = (const float4*)&s->fs[wid][0];
        const float4* ff4 = (const float4*)&s->ff[wid][0];
#pragma unroll
        for (int q = 0; q < CIN / 4; q++) {
            float4 a  = fs4[q];
            float4 cf = ff4[q];
            o += a.x  * s->b2s[(q * 4 + 0) * 32 + lane];
            o += a.y  * s->b2s[(q * 4 + 1) * 32 + lane];
            o += a.z  * s->b2s[(q * 4 + 2) * 32 + lane];
            o += a.w  * s->b2s[(q * 4 + 3) * 32 + lane];
            o += cf.x * s->wsk[(q * 4 + 0) * 32 + lane];
            o += cf.y * s->wsk[(q * 4 + 1) * 32 + lane];
            o += cf.z * s->wsk[(q * 4 + 2) * 32 + lane];
            o += cf.w * s->wsk[(q * 4 + 3) * 32 + lane];
        }
        o += s->bsk[lane];

        oreg[ti] = o;                 // stays in registers until LN
        osum += o;
        osq  += o * o;
        __syncthreads();              // (3) union free for next tile
    }

    // ---- block-level stats reduction, then one global double atomic ----
    atomicAdd(&s->ssum[lane], osum);
    atomicAdd(&s->ssq[lane], osq);
    __syncthreads();
    if (tid < COUT)           atomicAdd(&g_stats[tid], (double)s->ssum[tid]);
    else if (tid < 2 * COUT)  atomicAdd(&g_stats[tid], (double)s->ssq[tid - COUT]);

    // ---- grid sync: all 148 blocks resident -> spin is safe ----
    if (tid == 0) {
        __threadfence();
        atomicAdd(&g_done, 1);
        while (atomicAdd(&g_done, 0) < NBP) __nanosleep(128);
    }
    __syncthreads();

    // ---- LayerNorm finalize from registers ----
    if (tid < COUT) {
        const volatile double* gs = g_stats;
        double n = (double)NPOS;
        double mean = gs[tid] / n;
        double var  = gs[COUT + tid] / n - mean * mean;
        float rstd = rsqrtf((float)var + EPSV);
        float g = gamma[tid] * rstd;
        s->sc[tid] = g;
        s->sb[tid] = beta[tid] - g * (float)mean;
    }
    __syncthreads();

    float scv = s->sc[lane], sbv = s->sb[lane];
#pragma unroll
    for (int ti = 0; ti < MAXT; ti++) {
        int tile = blockIdx.x + ti * NBP;
        if (tile >= NTILE) break;
        int p = tile * NWB + wid;
        out[(size_t)p * COUT + lane] = oreg[ti] * scv + sbv;
    }

    // ---- reset state for next graph replay (last block only) ----
    __syncthreads();
    if (tid == 0) {
        __threadfence();
        int old = atomicAdd(&g_fin, 1);
        if (old == NBP - 1) {
            for (int i = 0; i < 2 * COUT; i++) g_stats[i] = 0.0;
            __threadfence();
            g_done = 0;
            g_fin  = 0;
        }
    }
}

// ---------------------------------------------------------------------------
extern "C" void kernel_launch(void* const* d_in, const int* in_sizes, int n_in,
                              void* d_out, int out_size) {
    const float* times    = (const float*)d_in[0];
    const float* features = (const float*)d_in[1];
    const void*  mask     = d_in[2];
    const float* W1    = (const float*)d_in[3];
    const float* b1    = (const float*)d_in[4];
    const float* W2    = (const float*)d_in[5];
    const float* b2    = (const float*)d_in[6];
    const float* Wskip = (const float*)d_in[7];
    const float* bskip = (const float*)d_in[8];
    const float* gamma = (const float*)d_in[9];
    const float* beta  = (const float*)d_in[10];
    float* out = (float*)d_out;

    cudaFuncSetAttribute(kpers, cudaFuncAttributeMaxDynamicSharedMemorySize,
                         (int)sizeof(SmemT));

    kpers<<<NBP, THREADS, sizeof(SmemT)>>>(times, features, mask, W1, b1,
                                           W2, b2, Wskip, bskip, gamma, beta,
                                           out);
}

// round 10
// speedup vs baseline: 1.1058x; 1.1058x over previous
#include <cuda_runtime.h>
#include <math.h>

#define BS 4
#define LEN 2048
#define CIN 32
#define COUT 32
#define HIDDIM 64
#define KTAP 8
#define PADL 7
#define NPOS (BS * LEN)
#define RDIM (CIN * HIDDIM)      // 2048
#define EPSV 1e-5f
#define NWB 16                    // positions per block (2 warps per position)
#define THREADS 1024
#define NBLK (NPOS / NWB)         // 512
#define MSPITCH 34                // u64 pitch per channel (16B-aligned chunks)

typedef unsigned long long u64;

__device__ double g_stats[2 * COUT];
__device__ int    g_sync;

// ---- register-pure packed helpers ----
#define FMA2(d, a, b, c) \
    asm("fma.rn.f32x2 %0, %1, %2, %3;" : "=l"(d) : "l"(a), "l"(b), "l"(c))

__device__ __forceinline__ u64 pack2(float x, float y) {
    u64 d; asm("mov.b64 %0, {%1, %2};" : "=l"(d) : "f"(x), "f"(y)); return d;
}
__device__ __forceinline__ u64 packdup(float x) {
    u64 d; asm("mov.b64 %0, {%1, %1};" : "=l"(d) : "f"(x)); return d;
}
__device__ __forceinline__ void unpack2(u64 v, float& x, float& y) {
    asm("mov.b64 {%0, %1}, %2;" : "=f"(x), "=f"(y) : "l"(v));
}

// mask dtype hedge (byte 1 nonzero <=> 1-byte storage; else 4-byte words)
__device__ __forceinline__ bool mask_at(const void* m, int idx, bool byte_mode) {
    if (byte_mode) return ((const unsigned char*)m)[idx] != 0;
    return ((const unsigned int*)m)[idx] != 0u;
}

struct SmemT {
    float W1s[CIN * HIDDIM];      // 8KB
    float b1s[HIDDIM];
    float b2s[CIN * COUT];        // 4KB
    float wsk[CIN * COUT];        // 4KB
    float bsk[COUT];
    float ff[NWB][CIN];           // 2KB
    float fs[NWB][CIN];           // 2KB
    float ssum[COUT], ssq[COUT];
    int   pflag[NWB];
    union alignas(16) {
        struct {
            float teu[NWB][CIN][KTAP];    // 16KB
            float hb[NWB][KTAP][HIDDIM];  // 32KB
        } a;
        float red[32][NWB][COUT];         // 64KB (32 source warps)
    } u;
    u64 Msu[NWB][CIN * MSPITCH];  // 136KB
};                                // ~226KB total

// W2 strip for phase B: warp owns channel c=wid; chunk cc covers j=16cc..16cc+15
__device__ __forceinline__ void load_wq(const float* __restrict__ W2,
                                        int wid, int lane, int cc, u64* wq) {
    const float* w2base = W2 + (size_t)(cc * 16) * (CIN * COUT) + wid * COUT + lane;
#pragma unroll
    for (int q = 0; q < 8; q++) {
        float w0 = w2base[(2 * q) * (CIN * COUT)];
        float w1 = w2base[(2 * q + 1) * (CIN * COUT)];
        wq[q] = pack2(w0, w1);
    }
}

__global__ __launch_bounds__(THREADS, 1)
void kfused(const float* __restrict__ times,
            const float* __restrict__ features,
            const void*  __restrict__ mask,
            const float* __restrict__ W1,
            const float* __restrict__ b1,
            const float* __restrict__ W2,
            const float* __restrict__ b2,
            const float* __restrict__ Wskip,
            const float* __restrict__ bskip,
            float* __restrict__ out) {
    extern __shared__ char smem_raw[];
    SmemT* s = (SmemT*)smem_raw;

    int tid  = threadIdx.x;
    int wid  = tid >> 5;          // 0..31
    int lane = tid & 31;
    int pos  = wid >> 1;          // 0..15 (position within tile)
    int jh   = wid & 1;           // j-half owned in phase A

    // ---- stage constants ----
    for (int i = tid; i < CIN * HIDDIM; i += THREADS) s->W1s[i] = W1[i];
    for (int i = tid; i < CIN * COUT; i += THREADS) {
        s->b2s[i] = b2[i];
        s->wsk[i] = Wskip[i];
    }
    if (tid < HIDDIM) s->b1s[tid] = b1[tid];
    if (tid < COUT) {
        s->bsk[tid]  = bskip[tid];
        s->ssum[tid] = 0.0f;
        s->ssq[tid]  = 0.0f;
    }
    __syncthreads();

    // ================= phase A: 2 warps per position =======================
    int p = blockIdx.x * NWB + pos;
    int b = p >> 11;
    int t = p & (LEN - 1);

    bool byte_mode = ((const unsigned char*)mask)[1] != 0;
    bool mask_t = mask_at(mask, p, byte_mode);
    float t_here = times[p];

    if (jh == 0) s->ff[pos][lane] = features[(size_t)p * CIN + lane];

    unsigned vmask = 0;
#pragma unroll
    for (int k = 0; k < KTAP; k++) {
        int idx = t - PADL + k;
        bool dm = mask_t && (idx >= 0);
        if (dm) dm = mask_at(mask, b * LEN + idx, byte_mode);
        if (dm) vmask |= (1u << k);
    }
    bool any = (vmask != 0);
    float fsum = 0.0f;

    if (any) {
        // --- te for all taps (lane = channel i); both warps duplicate ---
        float inv_pos = __expf(-(float)(lane >> 1) * (9.210340371976184f / 16.0f));
        float phase   = (lane & 1) ? 1.5707963267948966f : 0.0f;
        float fk[KTAP];
#pragma unroll
        for (int k = 0; k < KTAP; k++) {
            int idx = t - PADL + k;
            float te = 0.0f;
            fk[k] = 0.0f;
            if ((vmask >> k) & 1) {
                float dt = t_here - times[b * LEN + idx];
                te = __sinf(dt * inv_pos + phase);
                fk[k] = features[(size_t)(b * LEN + idx) * CIN + lane];
            }
            s->u.a.teu[pos][lane][k] = te;    // identical writes from both warps
            fsum += fk[k];
        }
        __syncwarp();                         // own writes cover own reads

        // --- h for all taps, this warp's j-half (j = jh*32 + lane) ---
        u64 hh[4];
#pragma unroll
        for (int g = 0; g < 4; g++) hh[g] = packdup(s->b1s[jh * 32 + lane]);
#pragma unroll
        for (int i = 0; i < CIN; i++) {
            u64 w = packdup(s->W1s[i * HIDDIM + jh * 32 + lane]);
            ulonglong2 t01 = *(const ulonglong2*)&s->u.a.teu[pos][i][0];
            ulonglong2 t23 = *(const ulonglong2*)&s->u.a.teu[pos][i][4];
            FMA2(hh[0], t01.x, w, hh[0]);
            FMA2(hh[1], t01.y, w, hh[1]);
            FMA2(hh[2], t23.x, w, hh[2]);
            FMA2(hh[3], t23.y, w, hh[3]);
        }
#pragma unroll
        for (int g = 0; g < 4; g++) {
            float a0, a1;
            unpack2(hh[g], a0, a1);           // taps 2g, 2g+1
            s->u.a.hb[pos][2 * g][jh * 32 + lane]     = fmaxf(a0, 0.0f);
            s->u.a.hb[pos][2 * g + 1][jh * 32 + lane] = fmaxf(a1, 0.0f);
        }
        __syncwarp();

        // --- M update (lane = channel), this warp's j-half ---
        u64 Macc[16];
#pragma unroll
        for (int q = 0; q < 16; q++) Macc[q] = 0ull;
#pragma unroll
        for (int k = 0; k < KTAP; k++) {
            if (!((vmask >> k) & 1)) continue;     // warp-uniform
            u64 f2 = packdup(fk[k]);
            const ulonglong2* hp2 = (const ulonglong2*)&s->u.a.hb[pos][k][jh * 32];
#pragma unroll
            for (int q2 = 0; q2 < 8; q2++) {
                ulonglong2 hp = hp2[q2];           // broadcast LDS.128
                FMA2(Macc[2 * q2],     f2, hp.x, Macc[2 * q2]);
                FMA2(Macc[2 * q2 + 1], f2, hp.y, Macc[2 * q2 + 1]);
            }
        }
#pragma unroll
        for (int q = 0; q < 16; q++)
            s->Msu[pos][lane * MSPITCH + jh * 16 + q] = Macc[q];
    }
    if (jh == 0) {
        s->fs[pos][lane] = fsum;
        if (lane == 0) s->pflag[pos] = any ? 1 : 0;
    }

    // prefetch chunk 0's W2 strip — latency hidden by the barrier wait
    u64 wq[8];
    load_wq(W2, wid, lane, 0, wq);
    __syncthreads();                               // (1)

    // ================= phase B: warp = channel wid, rows j=0..63 ===========
    unsigned pfm = __ballot_sync(0xffffffffu, lane < NWB && s->pflag[lane]);

    u64 acc2[NWB];
#pragma unroll
    for (int q = 0; q < NWB; q++) acc2[q] = 0ull;

    for (int cc = 0; cc < 4; cc++) {
#pragma unroll
        for (int pp = 0; pp < NWB; pp++) {
            if (!((pfm >> pp) & 1)) continue;      // register test, warp-uniform
            const ulonglong2* mp =
                (const ulonglong2*)&s->Msu[pp][wid * MSPITCH + cc * 8];
#pragma unroll
            for (int q2 = 0; q2 < 4; q2++) {
                ulonglong2 m = mp[q2];             // broadcast LDS.128
                FMA2(acc2[pp], m.x, wq[2 * q2],     acc2[pp]);
                FMA2(acc2[pp], m.y, wq[2 * q2 + 1], acc2[pp]);
            }
        }
        if (cc < 3) load_wq(W2, wid, lane, cc + 1, wq);
    }
#pragma unroll
    for (int pp = 0; pp < NWB; pp++) {
        float lo, hi;
        unpack2(acc2[pp], lo, hi);
        s->u.red[wid][pp][lane] = lo + hi;
    }
    __syncthreads();                               // (2)

    // ================= epilogue: jh==0 warp finalizes its position =========
    if (jh == 0) {
        float o = 0.0f;
#pragma unroll
        for (int w = 0; w < 32; w++) o += s->u.red[w][pos][lane];

        const float4* fs4 = (const float4*)&s->fs[pos][0];
        const float4* ff4 = (const float4*)&s->ff[pos][0];
#pragma unroll
        for (int q = 0; q < CIN / 4; q++) {
            float4 a  = fs4[q];
            float4 cf = ff4[q];
            o += a.x  * s->b2s[(q * 4 + 0) * 32 + lane];
            o += a.y  * s->b2s[(q * 4 + 1) * 32 + lane];
            o += a.z  * s->b2s[(q * 4 + 2) * 32 + lane];
            o += a.w  * s->b2s[(q * 4 + 3) * 32 + lane];
            o += cf.x * s->wsk[(q * 4 + 0) * 32 + lane];
            o += cf.y * s->wsk[(q * 4 + 1) * 32 + lane];
            o += cf.z * s->wsk[(q * 4 + 2) * 32 + lane];
            o += cf.w * s->wsk[(q * 4 + 3) * 32 + lane];
        }
        o += s->bsk[lane];

        out[(size_t)p * COUT + lane] = o;

        atomicAdd(&s->ssum[lane], o);
        atomicAdd(&s->ssq[lane], o * o);
    }
    __syncthreads();
    if (tid < COUT)           atomicAdd(&g_stats[tid], (double)s->ssum[tid]);
    else if (tid < 2 * COUT)  atomicAdd(&g_stats[tid], (double)s->ssq[tid - COUT]);
}

// ---------------------------------------------------------------------------
// K3: LayerNorm finalize; per-channel scale/bias once per block.
// Last-arriving block re-zeros g_stats for the next graph replay.
// ---------------------------------------------------------------------------
__global__ void k3(float* __restrict__ out,
                   const float* __restrict__ gamma,
                   const float* __restrict__ beta) {
    __shared__ float sc[COUT], sb[COUT];
    int tid = threadIdx.x;
    if (tid < COUT) {
        double n = (double)NPOS;
        double mean = g_stats[tid] / n;
        double var  = g_stats[COUT + tid] / n - mean * mean;
        float rstd = rsqrtf((float)var + EPSV);
        float g = gamma[tid] * rstd;
        sc[tid] = g;
        sb[tid] = beta[tid] - g * (float)mean;
    }
    __syncthreads();

    int e4 = blockIdx.x * blockDim.x + tid;
    if (e4 < NPOS * COUT / 4) {
        int o0 = (e4 * 4) & (COUT - 1);
        float4 v = ((const float4*)out)[e4];
        v.x = v.x * sc[o0]     + sb[o0];
        v.y = v.y * sc[o0 + 1] + sb[o0 + 1];
        v.z = v.z * sc[o0 + 2] + sb[o0 + 2];
        v.w = v.w * sc[o0 + 3] + sb[o0 + 3];
        ((float4*)out)[e4] = v;
    }
    __syncthreads();
    if (tid == 0) {
        __threadfence();
        int old = atomicAdd(&g_sync, 1);
        if (old == (int)gridDim.x - 1) {
            for (int i = 0; i < 2 * COUT; i++) g_stats[i] = 0.0;
            __threadfence();
            g_sync = 0;
        }
    }
}

// ---------------------------------------------------------------------------
extern "C" void kernel_launch(void* const* d_in, const int* in_sizes, int n_in,
                              void* d_out, int out_size) {
    const float* times    = (const float*)d_in[0];
    const float* features = (const float*)d_in[1];
    const void*  mask     = d_in[2];
    const float* W1    = (const float*)d_in[3];
    const float* b1    = (const float*)d_in[4];
    const float* W2    = (const float*)d_in[5];
    const float* b2    = (const float*)d_in[6];
    const float* Wskip = (const float*)d_in[7];
    const float* bskip = (const float*)d_in[8];
    const float* gamma = (const float*)d_in[9];
    const float* beta  = (const float*)d_in[10];
    float* out = (float*)d_out;

    cudaFuncSetAttribute(kfused, cudaFuncAttributeMaxDynamicSharedMemorySize,
                         (int)sizeof(SmemT));

    kfused<<<NBLK, THREADS, sizeof(SmemT)>>>(times, features, mask, W1, b1,
                                             W2, b2, Wskip, bskip, out);
    k3<<<(NPOS * COUT / 4 + 255) / 256, 256>>>(out, gamma, beta);
}